// round 6
// baseline (speedup 1.0000x reference)
#include <cuda_runtime.h>
#include <cuda_bf16.h>
#include <math.h>
#include <stdint.h>

#define NB  8
#define NC  256
#define NC2 128
#define NHW 4096

// ---------------------------------------------------------------------------
// Scratch (device globals; no allocation allowed)
// ---------------------------------------------------------------------------
__device__ __nv_bfloat16 g_X[(size_t)NB * NHW * NC];    // x transposed [b][n][c]
__device__ __nv_bfloat16 g_Q[(size_t)NB * NHW * NC2];   // [b][n][c], pre-scaled
__device__ __nv_bfloat16 g_K[(size_t)NB * NHW * NC2];   // [b][n][c]
__device__ __nv_bfloat16 g_V[(size_t)NB * NC2 * NHW];   // [b][c][n]
__device__ __nv_bfloat16 g_Yb[(size_t)NB * NHW * NC2];  // attn out [b][n][c]
__device__ __nv_bfloat16 g_Wb[3 * NC2 * NC];            // theta/phi/g weights bf16
__device__ __nv_bfloat16 g_Wob[NC * NC2];               // w_out bf16

// ---------------------------------------------------------------------------
// Helpers
// ---------------------------------------------------------------------------
__device__ __forceinline__ uint32_t smem_u32(const void* p) {
    uint32_t a;
    asm("{ .reg .u64 t; cvta.to.shared.u64 t, %1; cvt.u32.u64 %0, t; }" : "=r"(a) : "l"(p));
    return a;
}
__device__ __forceinline__ void cp_async16(uint32_t dst, const void* src) {
    asm volatile("cp.async.cg.shared.global [%0], [%1], 16;" :: "r"(dst), "l"(src) : "memory");
}
#define CP_COMMIT() asm volatile("cp.async.commit_group;" ::: "memory")
#define CP_WAIT1()  asm volatile("cp.async.wait_group 1;" ::: "memory")
#define CP_WAIT0()  asm volatile("cp.async.wait_group 0;" ::: "memory")

__device__ __forceinline__ void ldmx4(uint32_t addr, uint32_t& r0, uint32_t& r1,
                                      uint32_t& r2, uint32_t& r3) {
    asm volatile("ldmatrix.sync.aligned.m8n8.x4.shared.b16 {%0,%1,%2,%3}, [%4];"
                 : "=r"(r0), "=r"(r1), "=r"(r2), "=r"(r3) : "r"(addr));
}
__device__ __forceinline__ void mma16816(float* c, const uint32_t* a,
                                         uint32_t b0, uint32_t b1) {
    asm volatile(
        "mma.sync.aligned.m16n8k16.row.col.f32.bf16.bf16.f32 "
        "{%0,%1,%2,%3}, {%4,%5,%6,%7}, {%8,%9}, {%0,%1,%2,%3};"
        : "+f"(c[0]), "+f"(c[1]), "+f"(c[2]), "+f"(c[3])
        : "r"(a[0]), "r"(a[1]), "r"(a[2]), "r"(a[3]), "r"(b0), "r"(b1));
}
__device__ __forceinline__ float fast_exp2(float x) {
    float r; asm("ex2.approx.f32 %0, %1;" : "=f"(r) : "f"(x)); return r;
}
__device__ __forceinline__ uint32_t packbf(float a, float b) {
    __nv_bfloat162 t = __floats2bfloat162_rn(a, b);
    return *(uint32_t*)&t;
}

// log2(e) / sqrt(128)
#define QSCALE 0.12751491563218832f

// ---------------------------------------------------------------------------
// Kernel W: convert all weights fp32 -> bf16 once. grid 4, 256 thr.
// blocks 0..2: w_theta/w_phi/w_g [128][256] -> g_Wb; block 3: w_out -> g_Wob.
// ---------------------------------------------------------------------------
__global__ __launch_bounds__(256) void wconv_kernel(
    const float* __restrict__ w_theta, const float* __restrict__ w_phi,
    const float* __restrict__ w_g,     const float* __restrict__ w_out)
{
    const int mat = blockIdx.x;
    const float* src = (mat == 0) ? w_theta : (mat == 1) ? w_phi
                     : (mat == 2) ? w_g : w_out;
    __nv_bfloat16* dst = (mat < 3) ? (g_Wb + (size_t)mat * NC2 * NC) : g_Wob;
    const int tid = threadIdx.x;
#pragma unroll
    for (int p = 0; p < 32; p++) {
        int id = tid + p * 256;          // 8192 float4 = 32768 elems
        float4 v = *(const float4*)(src + (size_t)id * 4);
        uint2 o;
        o.x = packbf(v.x, v.y);
        o.y = packbf(v.z, v.w);
        *(uint2*)(dst + (size_t)id * 4) = o;
    }
}

// ---------------------------------------------------------------------------
// Kernel 0: x [b][c][n] fp32 -> g_X [b][n][c] bf16. grid (64, 4, 8), 128 thr.
// ---------------------------------------------------------------------------
__global__ __launch_bounds__(128) void convert_kernel(const float* __restrict__ x)
{
    __shared__ float sm[64][68];
    const int n0 = blockIdx.x * 64;
    const int c0 = blockIdx.y * 64;
    const int bb = blockIdx.z;
    const int tid = threadIdx.x;
    const float* xb = x + (size_t)bb * NC * NHW;

#pragma unroll
    for (int p = 0; p < 8; p++) {
        int id = tid + p * 128;
        int row = id >> 4;
        int q = id & 15;
        *(float4*)&sm[row][q * 4] =
            *(const float4*)(xb + (size_t)(c0 + row) * NHW + n0 + q * 4);
    }
    __syncthreads();

    __nv_bfloat16* dst = g_X + (size_t)bb * NHW * NC;
#pragma unroll
    for (int p = 0; p < 4; p++) {
        int id = tid + p * 128;
        int n = id >> 3;
        int q = id & 7;
        uint32_t pk[4];
#pragma unroll
        for (int h = 0; h < 4; h++)
            pk[h] = packbf(sm[q * 8 + 2 * h][n], sm[q * 8 + 2 * h + 1][n]);
        *(uint4*)(dst + (size_t)(n0 + n) * NC + c0 + q * 8) =
            make_uint4(pk[0], pk[1], pk[2], pk[3]);
    }
}

// ---------------------------------------------------------------------------
// Kernel 1: proj GEMM (bf16 mma). grid (64, 3, 8), 128 thr (4 warps).
// C[o 128][n 64] = sum_c W[o][c] * X[n][c], K=256 smem resident, both cp.async.
// smem: Ws bf16[128][264] (67584) | Xs bf16[64][264] (33792) -> 2 CTAs/SM.
// ---------------------------------------------------------------------------
#define PRW 264
#define PROJ_SMEM (128 * PRW * 2 + 64 * PRW * 2)   // 101376

__global__ __launch_bounds__(128) void proj_mma(
    const float* __restrict__ b_theta, const float* __restrict__ b_phi,
    const float* __restrict__ b_g)
{
    extern __shared__ char dsm[];
    const uint32_t ws = smem_u32(dsm);
    const uint32_t xs = ws + 128 * PRW * 2;

    const int n0  = blockIdx.x * 64;
    const int mat = blockIdx.y;
    const int bb  = blockIdx.z;
    const float* bias = (mat == 0) ? b_theta : (mat == 1 ? b_phi : b_g);

    const int tid  = threadIdx.x;
    const int warp = tid >> 5, lane = tid & 31;

    // Load W tile [128 o][256 c] bf16 via cp.async (4096 chunks, 32/thread)
    {
        const __nv_bfloat16* src = g_Wb + (size_t)mat * NC2 * NC;
#pragma unroll
        for (int p = 0; p < 32; p++) {
            int id = tid + p * 128;
            int row = id >> 5, ch = id & 31;
            cp_async16(ws + row * (PRW * 2) + ch * 16,
                       src + (size_t)row * NC + ch * 8);
        }
    }
    // Load X tile [64 n][256 c] bf16 (2048 chunks, 16/thread)
    {
        const __nv_bfloat16* src = g_X + (size_t)bb * NHW * NC + (size_t)n0 * NC;
#pragma unroll
        for (int p = 0; p < 16; p++) {
            int id = tid + p * 128;
            int row = id >> 5, ch = id & 31;
            cp_async16(xs + row * (PRW * 2) + ch * 16,
                       src + (size_t)row * NC + ch * 8);
        }
    }
    CP_COMMIT();
    CP_WAIT0();
    __syncthreads();

    const int g = lane >> 3, row = lane & 7;
    const uint32_t abase = ws + (warp * 32 + (g & 1) * 8 + row) * (PRW * 2)
                              + ((g >> 1) * 8) * 2;
    const uint32_t bfo = xs + ((g >> 1) * 8 + row) * (PRW * 2) + ((g & 1) * 8) * 2;

    float acc[2][8][4];
#pragma unroll
    for (int f = 0; f < 2; f++)
#pragma unroll
        for (int j = 0; j < 8; j++)
#pragma unroll
            for (int q = 0; q < 4; q++) acc[f][j][q] = 0.f;

#pragma unroll
    for (int ks = 0; ks < 16; ks++) {
        uint32_t a0[4], a1[4];
        ldmx4(abase + ks * 32, a0[0], a0[1], a0[2], a0[3]);
        ldmx4(abase + 16 * (PRW * 2) + ks * 32, a1[0], a1[1], a1[2], a1[3]);
#pragma unroll
        for (int nt = 0; nt < 4; nt++) {
            uint32_t b0, b1, b2, b3;
            ldmx4(bfo + nt * 16 * (PRW * 2) + ks * 32, b0, b1, b2, b3);
            mma16816(acc[0][2 * nt],     a0, b0, b1);
            mma16816(acc[0][2 * nt + 1], a0, b2, b3);
            mma16816(acc[1][2 * nt],     a1, b0, b1);
            mma16816(acc[1][2 * nt + 1], a1, b2, b3);
        }
    }
    __syncthreads();

    // Stage C (+bias, *scale) into fp32 smem [o 128][n 64+4]
    float* es = (float*)dsm;
    const float sc = (mat == 0) ? QSCALE : 1.0f;
#pragma unroll
    for (int f = 0; f < 2; f++) {
        int mb = warp * 32 + f * 16 + (lane >> 2);
        float bv0 = bias[mb] * sc;
        float bv1 = bias[mb + 8] * sc;
#pragma unroll
        for (int j = 0; j < 8; j++) {
            int n = j * 8 + (lane & 3) * 2;
            es[mb * 68 + n]           = acc[f][j][0] * sc + bv0;
            es[mb * 68 + n + 1]       = acc[f][j][1] * sc + bv0;
            es[(mb + 8) * 68 + n]     = acc[f][j][2] * sc + bv1;
            es[(mb + 8) * 68 + n + 1] = acc[f][j][3] * sc + bv1;
        }
    }
    __syncthreads();

    if (mat < 2) {
        // store [n][c]: 64 rows x 16 uint4 (1024 chunks, 8/thread)
        __nv_bfloat16* dst = (mat == 0 ? g_Q : g_K) + (size_t)bb * NHW * NC2;
#pragma unroll
        for (int p = 0; p < 8; p++) {
            int id = tid + p * 128;
            int n = id >> 4, q = id & 15;
            uint32_t pk[4];
#pragma unroll
            for (int h = 0; h < 4; h++)
                pk[h] = packbf(es[(q * 8 + 2 * h) * 68 + n],
                               es[(q * 8 + 2 * h + 1) * 68 + n]);
            *(uint4*)(dst + (size_t)(n0 + n) * NC2 + q * 8) =
                make_uint4(pk[0], pk[1], pk[2], pk[3]);
        }
    } else {
        // store [c][n]: 128 rows x 8 uint4 (1024 chunks, 8/thread)
        __nv_bfloat16* dst = g_V + (size_t)bb * NC2 * NHW;
#pragma unroll
        for (int p = 0; p < 8; p++) {
            int id = tid + p * 128;
            int r = id >> 3, q = id & 7;
            uint32_t pk[4];
#pragma unroll
            for (int h = 0; h < 4; h++)
                pk[h] = packbf(es[r * 68 + q * 8 + 2 * h],
                               es[r * 68 + q * 8 + 2 * h + 1]);
            *(uint4*)(dst + (size_t)r * NHW + n0 + q * 8) =
                make_uint4(pk[0], pk[1], pk[2], pk[3]);
        }
    }
}

// ---------------------------------------------------------------------------
// Kernel 2: bf16 mma.sync flash attention (no running max; fp32 row-sum).
// grid (64, 8), 128 threads (4 warps x 16 query rows). BC=64 keys per tile.
// ---------------------------------------------------------------------------
#define KROW 136
#define VROW 72
#define QBYTES  (64 * KROW * 2)
#define KBYTES  (64 * KROW * 2)
#define VBYTES  (128 * VROW * 2)
#define ATTN_SMEM (QBYTES + 2 * KBYTES + 2 * VBYTES)   // 89088

__global__ __launch_bounds__(128, 2) void attn_kernel()
{
    extern __shared__ char dsm[];
    const uint32_t base = smem_u32(dsm);
    const uint32_t qsm = base;
    const uint32_t ksm[2] = { base + QBYTES, base + QBYTES + KBYTES };
    const uint32_t vsm[2] = { base + QBYTES + 2 * KBYTES,
                              base + QBYTES + 2 * KBYTES + VBYTES };

    const int tid  = threadIdx.x;
    const int warp = tid >> 5, lane = tid & 31;
    const int n0 = blockIdx.x * 64;
    const int bb = blockIdx.y;
    const __nv_bfloat16* Qg = g_Q + (size_t)bb * NHW * NC2;
    const __nv_bfloat16* Kg = g_K + (size_t)bb * NHW * NC2;
    const __nv_bfloat16* Vg = g_V + (size_t)bb * NC2 * NHW;

    const int qk_row = tid >> 4;
    const int qk_co  = (tid & 15) * 8;
    const int v_row  = tid >> 3;
    const int v_co   = (tid & 7) * 8;

#define LOAD_QK(dstbase, srcbase) do {                                        \
    const __nv_bfloat16* _s = (srcbase) + (size_t)qk_row * NC2 + qk_co;       \
    uint32_t _d = (dstbase) + qk_row * (KROW * 2) + qk_co * 2;                \
    _Pragma("unroll")                                                         \
    for (int p = 0; p < 8; p++)                                               \
        cp_async16(_d + p * 8 * (KROW * 2), _s + (size_t)p * 8 * NC2);        \
} while (0)

#define LOAD_V(dstbase, m0) do {                                              \
    const __nv_bfloat16* _s = Vg + (size_t)v_row * NHW + (m0) + v_co;         \
    uint32_t _d = (dstbase) + v_row * (VROW * 2) + v_co * 2;                  \
    _Pragma("unroll")                                                         \
    for (int p = 0; p < 8; p++)                                               \
        cp_async16(_d + p * 16 * (VROW * 2), _s + (size_t)p * 16 * NHW);      \
} while (0)

    LOAD_QK(qsm, Qg + (size_t)n0 * NC2);
    LOAD_QK(ksm[0], Kg);
    LOAD_V(vsm[0], 0);
    CP_COMMIT();
    LOAD_QK(ksm[1], Kg + (size_t)64 * NC2);
    LOAD_V(vsm[1], 64);
    CP_COMMIT();

    const int g   = lane >> 3;
    const int row = lane & 7;
    const uint32_t qbase = qsm + (warp * 16 + (g & 1) * 8 + row) * (KROW * 2)
                               + ((g >> 1) * 8) * 2;
    const uint32_t kfoff = ((g >> 1) * 8 + row) * (KROW * 2) + ((g & 1) * 8) * 2;
    const uint32_t vfoff = ((g >> 1) * 8 + row) * (VROW * 2) + ((g & 1) * 8) * 2;

    uint32_t qf[8][4];
    float o[16][4];
    float lsum0 = 0.f, lsum1 = 0.f;
#pragma unroll
    for (int i = 0; i < 16; i++)
#pragma unroll
        for (int j = 0; j < 4; j++) o[i][j] = 0.f;

    for (int kt = 0; kt < 64; kt++) {
        CP_WAIT1();
        __syncthreads();
        if (kt == 0) {
#pragma unroll
            for (int ks = 0; ks < 8; ks++)
                ldmx4(qbase + ks * 32, qf[ks][0], qf[ks][1], qf[ks][2], qf[ks][3]);
        }
        const uint32_t kb = ksm[kt & 1] + kfoff;
        const uint32_t vb = vsm[kt & 1] + vfoff;

        float s[8][4];
#pragma unroll
        for (int i = 0; i < 8; i++)
#pragma unroll
            for (int j = 0; j < 4; j++) s[i][j] = 0.f;
#pragma unroll
        for (int ks = 0; ks < 8; ks++) {
#pragma unroll
            for (int nt2 = 0; nt2 < 4; nt2++) {
                uint32_t b0, b1, b2, b3;
                ldmx4(kb + nt2 * 16 * (KROW * 2) + ks * 32, b0, b1, b2, b3);
                mma16816(s[2 * nt2],     qf[ks], b0, b1);
                mma16816(s[2 * nt2 + 1], qf[ks], b2, b3);
            }
        }

        uint32_t a[4][4];
#pragma unroll
        for (int nt = 0; nt < 8; nt++) {
            float e0 = fast_exp2(s[nt][0]);
            float e1 = fast_exp2(s[nt][1]);
            float e2 = fast_exp2(s[nt][2]);
            float e3 = fast_exp2(s[nt][3]);
            lsum0 += e0 + e1;
            lsum1 += e2 + e3;
            a[nt >> 1][(nt & 1) * 2]     = packbf(e0, e1);
            a[nt >> 1][(nt & 1) * 2 + 1] = packbf(e2, e3);
        }

#pragma unroll
        for (int ks = 0; ks < 4; ks++) {
#pragma unroll
            for (int ct2 = 0; ct2 < 8; ct2++) {
                uint32_t b0, b1, b2, b3;
                ldmx4(vb + ct2 * 16 * (VROW * 2) + ks * 32, b0, b1, b2, b3);
                mma16816(o[2 * ct2],     a[ks], b0, b1);
                mma16816(o[2 * ct2 + 1], a[ks], b2, b3);
            }
        }

        __syncthreads();
        if (kt + 2 < 64) {
            LOAD_QK(ksm[kt & 1], Kg + (size_t)(kt + 2) * 64 * NC2);
            LOAD_V(vsm[kt & 1], (kt + 2) * 64);
        }
        CP_COMMIT();
    }

    CP_WAIT0();
    __syncthreads();

    lsum0 += __shfl_xor_sync(0xffffffffu, lsum0, 1);
    lsum0 += __shfl_xor_sync(0xffffffffu, lsum0, 2);
    lsum1 += __shfl_xor_sync(0xffffffffu, lsum1, 1);
    lsum1 += __shfl_xor_sync(0xffffffffu, lsum1, 2);
    const float inv0 = 1.0f / lsum0;
    const float inv1 = 1.0f / lsum1;

    float* es = (float*)dsm;
    const int m_lo = warp * 16 + (lane >> 2);
#pragma unroll
    for (int nt = 0; nt < 16; nt++) {
        int c = nt * 8 + (lane & 3) * 2;
        es[(c)     * 68 + m_lo]     = o[nt][0] * inv0;
        es[(c + 1) * 68 + m_lo]     = o[nt][1] * inv0;
        es[(c)     * 68 + m_lo + 8] = o[nt][2] * inv1;
        es[(c + 1) * 68 + m_lo + 8] = o[nt][3] * inv1;
    }
    __syncthreads();

    __nv_bfloat16* yb = g_Yb + (size_t)bb * NHW * NC2;
#pragma unroll
    for (int p = 0; p < 8; p++) {
        int id = tid + p * 128;
        int n = id >> 4, q = id & 15;
        uint32_t pk[4];
#pragma unroll
        for (int h = 0; h < 4; h++)
            pk[h] = packbf(es[(q * 8 + 2 * h) * 68 + n],
                           es[(q * 8 + 2 * h + 1) * 68 + n]);
        *(uint4*)(yb + (size_t)(n0 + n) * NC2 + q * 8) =
            make_uint4(pk[0], pk[1], pk[2], pk[3]);
    }
}

// ---------------------------------------------------------------------------
// Kernel 3: out conv (bf16 mma) + BN(eval) + residual.
// grid (32, 2, 8), 256 thr (8 warps, each 16 o-rows x 128 n).
// C[o 128][n 128] = sum_c Wout[o][c] * Y[n][c], K=128.
// smem: Ws bf16[128][136] | Ys bf16[128][136]  (69632 B -> 2 CTAs/SM)
// ---------------------------------------------------------------------------
#define ORW 136
#define OUT_SMEM (128 * ORW * 2 + 128 * ORW * 2)   // 69632

__global__ __launch_bounds__(256) void out_mma(
    const float* __restrict__ x,
    const float* __restrict__ b_out,
    const float* __restrict__ gamma, const float* __restrict__ beta,
    const float* __restrict__ rmean, const float* __restrict__ rvar,
    float* __restrict__ out)
{
    extern __shared__ char dsm[];
    const uint32_t ws = smem_u32(dsm);
    const uint32_t ys = ws + 128 * ORW * 2;

    const int n0  = blockIdx.x * 128;
    const int oc0 = blockIdx.y * 128;
    const int bb  = blockIdx.z;
    const int tid  = threadIdx.x;
    const int warp = tid >> 5, lane = tid & 31;

    // Load W half [128 o][128 c] bf16 (2048 chunks, 8/thread)
    {
        const __nv_bfloat16* src = g_Wob + (size_t)oc0 * NC2;
#pragma unroll
        for (int p = 0; p < 8; p++) {
            int id = tid + p * 256;
            int row = id >> 4, ch = id & 15;
            cp_async16(ws + row * (ORW * 2) + ch * 16,
                       src + (size_t)row * NC2 + ch * 8);
        }
    }
    // Load Y tile [128 n][128 c] bf16 (2048 chunks, 8/thread)
    {
        const __nv_bfloat16* src = g_Yb + (size_t)bb * NHW * NC2 + (size_t)n0 * NC2;
#pragma unroll
        for (int p = 0; p < 8; p++) {
            int id = tid + p * 256;
            int row = id >> 4, ch = id & 15;
            cp_async16(ys + row * (ORW * 2) + ch * 16,
                       src + (size_t)row * NC2 + ch * 8);
        }
    }
    CP_COMMIT();
    CP_WAIT0();
    __syncthreads();

    const int g = lane >> 3, row = lane & 7;
    const uint32_t abase = ws + (warp * 16 + (g & 1) * 8 + row) * (ORW * 2)
                              + ((g >> 1) * 8) * 2;
    const uint32_t bfo = ys + ((g >> 1) * 8 + row) * (ORW * 2) + ((g & 1) * 8) * 2;

    float acc[16][4];
#pragma unroll
    for (int j = 0; j < 16; j++)
#pragma unroll
        for (int q = 0; q < 4; q++) acc[j][q] = 0.f;

#pragma unroll
    for (int ks = 0; ks < 8; ks++) {
        uint32_t a0[4];
        ldmx4(abase + ks * 32, a0[0], a0[1], a0[2], a0[3]);
#pragma unroll
        for (int nt = 0; nt < 8; nt++) {
            uint32_t b0, b1, b2, b3;
            ldmx4(bfo + nt * 16 * (ORW * 2) + ks * 32, b0, b1, b2, b3);
            mma16816(acc[2 * nt],     a0, b0, b1);
            mma16816(acc[2 * nt + 1], a0, b2, b3);
        }
    }

    // BN + residual epilogue
    const float* xb = x + (size_t)bb * NC * NHW;
    float* ob = out + (size_t)bb * NC * NHW;
    const int m0 = oc0 + warp * 16 + (lane >> 2);
    const int m1 = m0 + 8;
    float iv0 = gamma[m0] * rsqrtf(rvar[m0] + 1e-5f);
    float iv1 = gamma[m1] * rsqrtf(rvar[m1] + 1e-5f);
    float sh0 = beta[m0] - rmean[m0] * iv0 + b_out[m0] * iv0;
    float sh1 = beta[m1] - rmean[m1] * iv1 + b_out[m1] * iv1;
#pragma unroll
    for (int j = 0; j < 16; j++) {
        int n = n0 + j * 8 + (lane & 3) * 2;
        float2 x0 = *(const float2*)(xb + (size_t)m0 * NHW + n);
        float2 x1 = *(const float2*)(xb + (size_t)m1 * NHW + n);
        float2 v0, v1;
        v0.x = x0.x + acc[j][0] * iv0 + sh0;
        v0.y = x0.y + acc[j][1] * iv0 + sh0;
        v1.x = x1.x + acc[j][2] * iv1 + sh1;
        v1.y = x1.y + acc[j][3] * iv1 + sh1;
        *(float2*)(ob + (size_t)m0 * NHW + n) = v0;
        *(float2*)(ob + (size_t)m1 * NHW + n) = v1;
    }
}

// ---------------------------------------------------------------------------
extern "C" void kernel_launch(void* const* d_in, const int* in_sizes, int n_in,
                              void* d_out, int out_size)
{
    const float* x       = (const float*)d_in[0];
    const float* w_theta = (const float*)d_in[1];
    const float* b_theta = (const float*)d_in[2];
    const float* w_phi   = (const float*)d_in[3];
    const float* b_phi   = (const float*)d_in[4];
    const float* w_g     = (const float*)d_in[5];
    const float* b_g     = (const float*)d_in[6];
    const float* w_out   = (const float*)d_in[7];
    const float* b_out   = (const float*)d_in[8];
    const float* gamma   = (const float*)d_in[9];
    const float* beta    = (const float*)d_in[10];
    const float* rmean   = (const float*)d_in[11];
    const float* rvar    = (const float*)d_in[12];
    float* out = (float*)d_out;

    cudaFuncSetAttribute(attn_kernel,
                         cudaFuncAttributeMaxDynamicSharedMemorySize, ATTN_SMEM);
    cudaFuncSetAttribute(proj_mma,
                         cudaFuncAttributeMaxDynamicSharedMemorySize, PROJ_SMEM);
    cudaFuncSetAttribute(out_mma,
                         cudaFuncAttributeMaxDynamicSharedMemorySize, OUT_SMEM);

    wconv_kernel<<<4, 256>>>(w_theta, w_phi, w_g, w_out);

    dim3 g0(NHW / 64, NC / 64, NB);
    convert_kernel<<<g0, 128>>>(x);

    dim3 g1(NHW / 64, 3, NB);
    proj_mma<<<g1, 128, PROJ_SMEM>>>(b_theta, b_phi, b_g);

    dim3 g2(NHW / 64, NB);
    attn_kernel<<<g2, 128, ATTN_SMEM>>>();

    dim3 g3(NHW / 128, 2, NB);
    out_mma<<<g3, 256, OUT_SMEM>>>(x, b_out, gamma, beta, rmean, rvar, out);
}